// round 1
// baseline (speedup 1.0000x reference)
#include <cuda_runtime.h>
#include <math.h>

#define BB 128
#define TT 512
#define DD 100
#define HH 100
#define G4 400
#define LL 25

// ---------------- device scratch (static; no runtime allocation) ----------------
__device__ float g_gin[2][TT][BB][G4];          // input projection + biases (209.7 MB)
__device__ float g_h[2][TT][BB][HH];            // hidden states, both dirs (52.4 MB)
__device__ float g_em[(size_t)BB * TT * LL];    // emissions [b][t][l] (6.6 MB)
__device__ float g_res[BB];                     // per-batch logZ - gold

// ---------------- helpers ----------------
__device__ __forceinline__ float sigf(float x) {
    return __fdividef(1.f, 1.f + __expf(-x));
}
__device__ __forceinline__ float tanh_fast(float x) {
    return __fdividef(2.f, 1.f + __expf(-2.f * x)) - 1.f;
}

// ================= Kernel 1: embedding lookup + input projection GEMM =================
// gin[dir][t][b][g] = sum_d emb[tok[b][t]][d] * w_ih[g][d] + b_ih[g] + b_hh[g]
// block: 32 rows (m = t*128 + b) x 800 cols (400 fwd + 400 bwd), 256 threads
__global__ void __launch_bounds__(256) k_input_proj(
    const int* __restrict__ tok, const float* __restrict__ emb,
    const float* __restrict__ wih_f, const float* __restrict__ wih_b,
    const float* __restrict__ bih_f, const float* __restrict__ bhh_f,
    const float* __restrict__ bih_b, const float* __restrict__ bhh_b)
{
    __shared__ float xs[32][100];
    __shared__ float wc[100][65];   // pad 65: conflict-free stores & loads
    const int m0 = blockIdx.x * 32;
    const int tid = threadIdx.x;

    // stage x tile (gathered embeddings)
    for (int i = tid; i < 32 * 100; i += 256) {
        int r = i / 100, d = i - r * 100;
        int m = m0 + r;
        int t = m >> 7, b = m & 127;
        int token = tok[b * TT + t];
        xs[r][d] = emb[token * DD + d];
    }
    __syncthreads();

    const int rp = (tid >> 4) * 2;   // row pair base 0..30
    const int cl = tid & 15;         // column lane 0..15 (cols cl + 16q)

    for (int ch = 0; ch < 13; ++ch) {
        const int c0 = ch * 64;
        // stage 64-col weight chunk, transposed: wc[d][cc] = W[col][d]
        for (int i = tid; i < 64 * 100; i += 256) {
            int cc = i / 100, d = i - cc * 100;
            int col = c0 + cc;
            float v = 0.f;
            if (col < 400)      v = wih_f[col * DD + d];
            else if (col < 800) v = wih_b[(col - 400) * DD + d];
            wc[d][cc] = v;
        }
        __syncthreads();

        float acc[2][4] = {{0.f,0.f,0.f,0.f},{0.f,0.f,0.f,0.f}};
        #pragma unroll 5
        for (int d = 0; d < 100; ++d) {
            float x0 = xs[rp][d];
            float x1 = xs[rp + 1][d];
            float w0 = wc[d][cl];
            float w1 = wc[d][cl + 16];
            float w2 = wc[d][cl + 32];
            float w3 = wc[d][cl + 48];
            acc[0][0] += x0 * w0; acc[0][1] += x0 * w1;
            acc[0][2] += x0 * w2; acc[0][3] += x0 * w3;
            acc[1][0] += x1 * w0; acc[1][1] += x1 * w1;
            acc[1][2] += x1 * w2; acc[1][3] += x1 * w3;
        }

        #pragma unroll
        for (int rr = 0; rr < 2; ++rr) {
            int m = m0 + rp + rr;
            int t = m >> 7, b = m & 127;
            #pragma unroll
            for (int q = 0; q < 4; ++q) {
                int col = c0 + cl + q * 16;
                if (col < 400) {
                    g_gin[0][t][b][col] = acc[rr][q] + bih_f[col] + bhh_f[col];
                } else if (col < 800) {
                    int c2 = col - 400;
                    g_gin[1][t][b][c2] = acc[rr][q] + bih_b[c2] + bhh_b[c2];
                }
            }
        }
        __syncthreads();
    }
}

// ================= Kernel 2: LSTM recurrence (both dirs, 2 batch elems / block) =================
// smem layout (floats): wsh[400*108] | gbuf[2*400] | hsm[2*100]
#define WSH_F   (400 * 108)
#define GBUF_F  (800)
#define HSM_F   (200)
#define REC_SMEM_BYTES ((WSH_F + GBUF_F + HSM_F) * 4)

__global__ void __launch_bounds__(400) k_lstm(
    const float* __restrict__ whh_f, const float* __restrict__ whh_b)
{
    extern __shared__ float sm[];
    float* wsh  = sm;                     // [400][108] padded rows (16B-aligned)
    float* gbuf = sm + WSH_F;             // [2][400] activated gates
    float* hsm  = sm + WSH_F + GBUF_F;    // [2][100] hidden state

    const int dir = blockIdx.y;
    const int b0  = blockIdx.x * 2;
    const int tid = threadIdx.x;          // 0..399 (= gate index)
    const float* whh = dir ? whh_b : whh_f;

    // load W_hh (row-major, row padded to 108 floats), vectorized
    for (int i = tid; i < 400 * 25; i += 400) {
        int g = i / 25, q = i - g * 25;
        float4 w4 = *(const float4*)(whh + g * 100 + q * 4);
        *(float4*)(wsh + g * 108 + q * 4) = w4;
    }
    if (tid < 200) hsm[tid] = 0.f;
    float c0 = 0.f, c1 = 0.f;
    __syncthreads();

    const int gate  = tid;
    const int gtype = gate / 100;         // 0:i 1:f 2:g 3:o
    const float* wrow = wsh + gate * 108;

    for (int s = 0; s < TT; ++s) {
        const int t = dir ? (TT - 1 - s) : s;
        float acc0 = g_gin[dir][t][b0][gate];
        float acc1 = g_gin[dir][t][b0 + 1][gate];
        #pragma unroll 5
        for (int q = 0; q < 25; ++q) {
            float4 w4 = *(const float4*)(wrow + q * 4);
            float4 h0 = *(const float4*)(hsm + q * 4);
            float4 h1 = *(const float4*)(hsm + 100 + q * 4);
            acc0 += w4.x * h0.x + w4.y * h0.y + w4.z * h0.z + w4.w * h0.w;
            acc1 += w4.x * h1.x + w4.y * h1.y + w4.z * h1.z + w4.w * h1.w;
        }
        float a0, a1;
        if (gtype == 2) { a0 = tanh_fast(acc0); a1 = tanh_fast(acc1); }
        else            { a0 = sigf(acc0);      a1 = sigf(acc1); }
        gbuf[gate]       = a0;
        gbuf[400 + gate] = a1;
        __syncthreads();

        if (tid < 100) {
            const int k = tid;
            float iv = gbuf[k], fv = gbuf[k + 100], gv = gbuf[k + 200], ov = gbuf[k + 300];
            c0 = fv * c0 + iv * gv;
            float h0v = ov * tanh_fast(c0);
            hsm[k] = h0v;
            g_h[dir][t][b0][k] = h0v;

            iv = gbuf[400 + k]; fv = gbuf[500 + k]; gv = gbuf[600 + k]; ov = gbuf[700 + k];
            c1 = fv * c1 + iv * gv;
            float h1v = ov * tanh_fast(c1);
            hsm[100 + k] = h1v;
            g_h[dir][t][b0 + 1][k] = h1v;
        }
        __syncthreads();
    }
}

// ================= Kernel 3: emissions = [h_f|h_b] . w_tag^T + b_tag =================
__global__ void __launch_bounds__(256) k_emit(
    const float* __restrict__ wtag, const float* __restrict__ btag)
{
    __shared__ float hs[32 * 200];
    __shared__ float wt[25 * 201];   // pad 201 -> conflict-free (gcd(201%32,32)=1)
    const int m0 = blockIdx.x * 32;
    const int tid = threadIdx.x;

    for (int i = tid; i < 25 * 200; i += 256) {
        int l = i / 200, k = i - l * 200;
        wt[l * 201 + k] = wtag[i];
    }
    for (int i = tid; i < 32 * 200; i += 256) {
        int r = i / 200, k = i - r * 200;
        int m = m0 + r;
        int t = m >> 7, b = m & 127;
        hs[r * 200 + k] = (k < 100) ? g_h[0][t][b][k] : g_h[1][t][b][k - 100];
    }
    __syncthreads();

    for (int o = tid; o < 800; o += 256) {
        int r = o / 25, l = o - r * 25;
        float s = btag[l];
        const float* hr = hs + r * 200;
        const float* wr = wt + l * 201;
        #pragma unroll 4
        for (int k = 0; k < 200; ++k) s += hr[k] * wr[k];
        int m = m0 + r;
        int t = m >> 7, b = m & 127;
        g_em[((size_t)b * TT + t) * LL + l] = s;
    }
}

// ================= Kernel 4: CRF NLL per batch element (1 warp / block) =================
__global__ void __launch_bounds__(32) k_crf(
    const float* __restrict__ trans, const float* __restrict__ strans,
    const float* __restrict__ etrans, const int* __restrict__ tags,
    const int* __restrict__ lengths)
{
    __shared__ float tr[25 * 25];
    __shared__ float alpha_s[32];
    const int b = blockIdx.x;
    const int lane = threadIdx.x;

    for (int i = lane; i < 625; i += 32) tr[i] = trans[i];
    __syncwarp();

    const int len = lengths[b];
    const int* tg = tags + b * TT;
    const float* em = g_em + (size_t)b * TT * LL;

    // ---- gold path score ----
    float gp = 0.f;
    for (int t = 1 + lane; t < TT; t += 32) {
        if (t < len) {
            int tp = tg[t - 1], tc = tg[t];
            gp += tr[tp * 25 + tc] + em[t * LL + tc];
        }
    }
    #pragma unroll
    for (int off = 16; off; off >>= 1) gp += __shfl_down_sync(0xffffffffu, gp, off);
    float gold = __shfl_sync(0xffffffffu, gp, 0);
    if (lane == 0) {
        int t0 = tg[0];
        gold += strans[t0] + em[t0];
        gold += etrans[tg[len - 1]];
    }
    gold = __shfl_sync(0xffffffffu, gold, 0);

    // ---- forward algorithm (log partition) ----
    float a = -1e30f;
    if (lane < LL) a = strans[lane] + em[lane];
    alpha_s[lane] = a;
    __syncwarp();

    for (int t = 1; t < TT; ++t) {
        float na = a;
        if (lane < LL && t < len) {
            float v[25];
            #pragma unroll
            for (int p = 0; p < 25; ++p) v[p] = alpha_s[p] + tr[p * 25 + lane];
            float m = v[0];
            #pragma unroll
            for (int p = 1; p < 25; ++p) m = fmaxf(m, v[p]);
            float ssum = 0.f;
            #pragma unroll
            for (int p = 0; p < 25; ++p) ssum += __expf(v[p] - m);
            na = m + __logf(ssum) + em[t * LL + lane];
        }
        __syncwarp();
        a = na;
        alpha_s[lane] = a;
        __syncwarp();
    }

    float vv = (lane < LL) ? (a + etrans[lane]) : -1e30f;
    float m = vv;
    #pragma unroll
    for (int off = 16; off; off >>= 1) m = fmaxf(m, __shfl_xor_sync(0xffffffffu, m, off));
    float e = __expf(vv - m);
    #pragma unroll
    for (int off = 16; off; off >>= 1) e += __shfl_xor_sync(0xffffffffu, e, off);
    float logZ = m + __logf(e);
    if (lane == 0) g_res[b] = logZ - gold;
}

// ================= Kernel 5: final fixed-order reduction =================
__global__ void __launch_bounds__(128) k_reduce(float* __restrict__ out)
{
    __shared__ float s[128];
    s[threadIdx.x] = g_res[threadIdx.x];
    __syncthreads();
    for (int st = 64; st > 0; st >>= 1) {
        if (threadIdx.x < st) s[threadIdx.x] += s[threadIdx.x + st];
        __syncthreads();
    }
    if (threadIdx.x == 0) out[0] = s[0];
}

// ================= launch =================
extern "C" void kernel_launch(void* const* d_in, const int* in_sizes, int n_in,
                              void* d_out, int out_size)
{
    const int*   tok     = (const int*)  d_in[0];
    const int*   tag     = (const int*)  d_in[1];
    const int*   lengths = (const int*)  d_in[2];
    const float* emb     = (const float*)d_in[3];
    const float* wih_f   = (const float*)d_in[4];
    const float* whh_f   = (const float*)d_in[5];
    const float* bih_f   = (const float*)d_in[6];
    const float* bhh_f   = (const float*)d_in[7];
    const float* wih_b   = (const float*)d_in[8];
    const float* whh_b   = (const float*)d_in[9];
    const float* bih_b   = (const float*)d_in[10];
    const float* bhh_b   = (const float*)d_in[11];
    const float* wtag    = (const float*)d_in[12];
    const float* btag    = (const float*)d_in[13];
    const float* trans   = (const float*)d_in[14];
    const float* strans  = (const float*)d_in[15];
    const float* etrans  = (const float*)d_in[16];
    float* out = (float*)d_out;

    cudaFuncSetAttribute(k_lstm, cudaFuncAttributeMaxDynamicSharedMemorySize,
                         REC_SMEM_BYTES);

    k_input_proj<<<2048, 256>>>(tok, emb, wih_f, wih_b, bih_f, bhh_f, bih_b, bhh_b);
    k_lstm<<<dim3(64, 2), 400, REC_SMEM_BYTES>>>(whh_f, whh_b);
    k_emit<<<2048, 256>>>(wtag, btag);
    k_crf<<<128, 32>>>(trans, strans, etrans, tag, lengths);
    k_reduce<<<1, 128>>>(out);
}

// round 2
// speedup vs baseline: 1.6746x; 1.6746x over previous
#include <cuda_runtime.h>
#include <math.h>

#define BB 128
#define TT 512
#define DD 100
#define HH 100
#define G4 400
#define LL 25

typedef unsigned long long ull;

// ---------------- device scratch (static; no runtime allocation) ----------------
__device__ float g_gin[2][TT][BB][G4];          // input projection + biases (209.7 MB)
__device__ float g_h[2][TT][BB][HH];            // hidden states, both dirs (52.4 MB)
__device__ float g_em[(size_t)BB * TT * LL];    // emissions [b][t][l] (6.6 MB)
__device__ float g_res[BB];                     // per-batch logZ - gold

// ---------------- helpers ----------------
__device__ __forceinline__ float sigf(float x) {
    return __fdividef(1.f, 1.f + __expf(-x));
}
__device__ __forceinline__ float tanh_fast(float x) {
    return __fdividef(2.f, 1.f + __expf(-2.f * x)) - 1.f;
}
// packed fp32x2 FMA (sm_103a FFMA2) — full fp32 precision, 2 FMA/instr
__device__ __forceinline__ ull ffma2(ull a, ull b, ull c) {
    ull d;
    asm("fma.rn.f32x2 %0, %1, %2, %3;" : "=l"(d) : "l"(a), "l"(b), "l"(c));
    return d;
}
__device__ __forceinline__ float2 u2f(ull u) {
    float2 f;
    asm("mov.b64 {%0, %1}, %2;" : "=f"(f.x), "=f"(f.y) : "l"(u));
    return f;
}

// ================= Kernel 1: embedding lookup + input projection GEMM =================
// C[m][col] = sum_d emb[tok(m)][d] * W[col][d] + bias[col],  m = t*128+b, col in [0,800)
// block: 128 rows x 64 cols, 128 threads, thread tile 8x8, f32x2 k-pair packing.
#define XS_STRIDE 102
#define PROJ_SMEM ((128 * XS_STRIDE + 64 * XS_STRIDE) * 4)

__global__ void __launch_bounds__(128) k_input_proj(
    const int* __restrict__ tok, const float* __restrict__ emb,
    const float* __restrict__ wih_f, const float* __restrict__ wih_b,
    const float* __restrict__ bih_f, const float* __restrict__ bhh_f,
    const float* __restrict__ bih_b, const float* __restrict__ bhh_b)
{
    extern __shared__ float psm[];
    float* xs = psm;                    // [128][102]
    float* wc = psm + 128 * XS_STRIDE;  // [64][102]
    const int m0 = blockIdx.x * 128;
    const int c0 = blockIdx.y * 64;
    const int tid = threadIdx.x;

    // stage x (gathered embeddings): thread <-> row
    {
        const int r = tid;
        const int m = m0 + r;
        const int t = m >> 7, b = m & 127;
        const int token = tok[b * TT + t];
        const float4* src = (const float4*)(emb + (size_t)token * DD);
        float* dst = xs + r * XS_STRIDE;
        #pragma unroll
        for (int q = 0; q < 25; ++q) {
            float4 v = src[q];
            *(float2*)(dst + 4 * q)     = make_float2(v.x, v.y);
            *(float2*)(dst + 4 * q + 2) = make_float2(v.z, v.w);
        }
    }
    // stage weight chunk (64 cols x 100)
    for (int i = tid; i < 64 * 25; i += 128) {
        const int cc = i / 25, q = i - cc * 25;
        const int col = c0 + cc;
        float4 v = make_float4(0.f, 0.f, 0.f, 0.f);
        if (col < 400)      v = *(const float4*)(wih_f + col * DD + 4 * q);
        else if (col < 800) v = *(const float4*)(wih_b + (col - 400) * DD + 4 * q);
        float* dst = wc + cc * XS_STRIDE + 4 * q;
        *(float2*)(dst)     = make_float2(v.x, v.y);
        *(float2*)(dst + 2) = make_float2(v.z, v.w);
    }
    __syncthreads();

    const int ct = tid >> 4;   // 0..7
    const int rt = tid & 15;   // 0..15 (rows rt + 16*i)

    ull acc[8][4][2];
    #pragma unroll
    for (int i = 0; i < 8; ++i)
        #pragma unroll
        for (int j = 0; j < 4; ++j) { acc[i][j][0] = 0ull; acc[i][j][1] = 0ull; }

    #pragma unroll 2
    for (int kp = 0; kp < 50; ++kp) {
        ull xv[8];
        #pragma unroll
        for (int i = 0; i < 8; ++i)
            xv[i] = *(const ull*)(xs + (rt + 16 * i) * XS_STRIDE + 2 * kp);
        ull wv[4][2];
        #pragma unroll
        for (int j = 0; j < 4; ++j) {
            #pragma unroll
            for (int e = 0; e < 2; ++e)
                wv[j][e] = *(const ull*)(wc + (2 * ct + 16 * j + e) * XS_STRIDE + 2 * kp);
        }
        #pragma unroll
        for (int i = 0; i < 8; ++i)
            #pragma unroll
            for (int j = 0; j < 4; ++j) {
                acc[i][j][0] = ffma2(xv[i], wv[j][0], acc[i][j][0]);
                acc[i][j][1] = ffma2(xv[i], wv[j][1], acc[i][j][1]);
            }
    }

    // store (float2 over adjacent cols; col even so never straddles dir boundary)
    #pragma unroll
    for (int i = 0; i < 8; ++i) {
        const int r = rt + 16 * i;
        const int m = m0 + r;
        const int t = m >> 7, b = m & 127;
        #pragma unroll
        for (int j = 0; j < 4; ++j) {
            const int col = c0 + 2 * ct + 16 * j;
            if (col < 800) {
                float2 s0 = u2f(acc[i][j][0]);
                float2 s1 = u2f(acc[i][j][1]);
                float r0 = s0.x + s0.y;
                float r1 = s1.x + s1.y;
                if (col < 400) {
                    r0 += bih_f[col] + bhh_f[col];
                    r1 += bih_f[col + 1] + bhh_f[col + 1];
                    *(float2*)(&g_gin[0][t][b][col]) = make_float2(r0, r1);
                } else {
                    const int c2 = col - 400;
                    r0 += bih_b[c2] + bhh_b[c2];
                    r1 += bih_b[c2 + 1] + bhh_b[c2 + 1];
                    *(float2*)(&g_gin[1][t][b][c2]) = make_float2(r0, r1);
                }
            }
        }
    }
}

// ================= Kernel 2: LSTM recurrence (W_hh in registers) =================
// 400 threads = 400 gates, 2 batch elems per block, grid (64, 2dirs) = 128 blocks.
__global__ void __launch_bounds__(400, 1) k_lstm(
    const float* __restrict__ whh_f, const float* __restrict__ whh_b)
{
    __shared__ __align__(16) float hsm[208];  // interleaved: [p][ h0(2) h1(2) ]
    __shared__ float gbuf[800];

    const int dir = blockIdx.y;
    const int b0  = blockIdx.x * 2;
    const int g   = threadIdx.x;              // gate 0..399
    const float* whh = (dir ? whh_b : whh_f) + g * 100;

    // weight row -> registers (50 packed f32x2)
    ull w[50];
    #pragma unroll
    for (int q = 0; q < 50; ++q) w[q] = *(const ull*)(whh + 2 * q);

    if (g < 52) *(float4*)(hsm + 4 * g) = make_float4(0.f, 0.f, 0.f, 0.f);
    float c0v = 0.f, c1v = 0.f;
    __syncthreads();

    const int gtype = g / 100;    // 0:i 1:f 2:g 3:o
    int t = dir ? (TT - 1) : 0;
    const int tstep = dir ? -1 : 1;
    float pre0 = g_gin[dir][t][b0][g];
    float pre1 = g_gin[dir][t][b0 + 1][g];

    for (int s = 0; s < TT; ++s, t += tstep) {
        // prefetch next step's gin (hides DRAM latency behind this step)
        float nx0 = 0.f, nx1 = 0.f;
        if (s + 1 < TT) {
            const int tn = t + tstep;
            nx0 = g_gin[dir][tn][b0][g];
            nx1 = g_gin[dir][tn][b0 + 1][g];
        }

        ull a0a = 0ull, a0b = 0ull, a1a = 0ull, a1b = 0ull;
        #pragma unroll
        for (int q = 0; q < 50; q += 2) {
            ulonglong2 ha = *(const ulonglong2*)(hsm + 4 * q);       // .x=h0 pair q, .y=h1 pair q
            ulonglong2 hb = *(const ulonglong2*)(hsm + 4 * q + 4);
            a0a = ffma2(w[q],     ha.x, a0a);
            a1a = ffma2(w[q],     ha.y, a1a);
            a0b = ffma2(w[q + 1], hb.x, a0b);
            a1b = ffma2(w[q + 1], hb.y, a1b);
        }
        float2 p0a = u2f(a0a), p0b = u2f(a0b), p1a = u2f(a1a), p1b = u2f(a1b);
        float acc0 = pre0 + (p0a.x + p0a.y) + (p0b.x + p0b.y);
        float acc1 = pre1 + (p1a.x + p1a.y) + (p1b.x + p1b.y);

        float v0, v1;
        if (gtype == 2) { v0 = tanh_fast(acc0); v1 = tanh_fast(acc1); }
        else            { v0 = sigf(acc0);      v1 = sigf(acc1); }
        gbuf[g]       = v0;
        gbuf[400 + g] = v1;
        __syncthreads();

        if (g < 100) {
            const int k = g;
            float iv = gbuf[k], fv = gbuf[k + 100], gv = gbuf[k + 200], ov = gbuf[k + 300];
            c0v = fv * c0v + iv * gv;
            float h0 = ov * tanh_fast(c0v);
            iv = gbuf[400 + k]; fv = gbuf[500 + k]; gv = gbuf[600 + k]; ov = gbuf[700 + k];
            c1v = fv * c1v + iv * gv;
            float h1 = ov * tanh_fast(c1v);
            const int p = k >> 1, e = k & 1;
            hsm[4 * p + e]     = h0;
            hsm[4 * p + 2 + e] = h1;
            g_h[dir][t][b0][k]     = h0;
            g_h[dir][t][b0 + 1][k] = h1;
        }
        pre0 = nx0; pre1 = nx1;
        __syncthreads();
    }
}

// ================= Kernel 3: emissions = [h_f|h_b] . w_tag^T + b_tag =================
#define HS_STRIDE 202
#define EMIT_SMEM ((128 * HS_STRIDE + 25 * HS_STRIDE) * 4)

__global__ void __launch_bounds__(320) k_emit(
    const float* __restrict__ wtag, const float* __restrict__ btag)
{
    extern __shared__ float esm[];
    float* hs = esm;                    // [128][202]
    float* wt = esm + 128 * HS_STRIDE;  // [25][202]
    const int tid = threadIdx.x;
    const int m0 = blockIdx.x * 128;

    for (int i = tid; i < 25 * 100; i += 320) {
        const int l = i / 100, kp = i - l * 100;
        *(float2*)(wt + l * HS_STRIDE + 2 * kp) = *(const float2*)(wtag + l * 200 + 2 * kp);
    }
    for (int i = tid; i < 128 * 100; i += 320) {
        const int r = i / 100, kp = i - r * 100;
        const int m = m0 + r;
        const int t = m >> 7, b = m & 127;
        const int k = 2 * kp;
        float2 v = (k < 100) ? *(const float2*)(&g_h[0][t][b][k])
                             : *(const float2*)(&g_h[1][t][b][k - 100]);
        *(float2*)(hs + r * HS_STRIDE + k) = v;
    }
    __syncthreads();

    const int rp = tid / 5;   // 0..63 -> rows {2rp, 2rp+1}
    const int lg = tid - rp * 5;  // labels {5lg..5lg+4}
    ull acc[2][5];
    #pragma unroll
    for (int rr = 0; rr < 2; ++rr)
        #pragma unroll
        for (int j = 0; j < 5; ++j) acc[rr][j] = 0ull;

    const float* h0p = hs + (2 * rp) * HS_STRIDE;
    const float* h1p = hs + (2 * rp + 1) * HS_STRIDE;
    #pragma unroll 4
    for (int kp = 0; kp < 100; ++kp) {
        ull hv0 = *(const ull*)(h0p + 2 * kp);
        ull hv1 = *(const ull*)(h1p + 2 * kp);
        #pragma unroll
        for (int j = 0; j < 5; ++j) {
            ull wv = *(const ull*)(wt + (5 * lg + j) * HS_STRIDE + 2 * kp);
            acc[0][j] = ffma2(hv0, wv, acc[0][j]);
            acc[1][j] = ffma2(hv1, wv, acc[1][j]);
        }
    }
    #pragma unroll
    for (int rr = 0; rr < 2; ++rr) {
        const int r = 2 * rp + rr;
        const int m = m0 + r;
        const int t = m >> 7, b = m & 127;
        #pragma unroll
        for (int j = 0; j < 5; ++j) {
            const int l = 5 * lg + j;
            float2 p = u2f(acc[rr][j]);
            g_em[((size_t)b * TT + t) * LL + l] = p.x + p.y + btag[l];
        }
    }
}

// ================= Kernel 4: CRF NLL (scaled-probability forward algorithm) =================
__global__ void __launch_bounds__(32) k_crf(
    const float* __restrict__ trans, const float* __restrict__ strans,
    const float* __restrict__ etrans, const int* __restrict__ tags,
    const int* __restrict__ lengths)
{
    __shared__ float E[640];    // exp(transitions) [p*25 + l]
    __shared__ float tr[640];   // raw transitions (gold path)
    __shared__ float As[32];
    const int b = blockIdx.x;
    const int lane = threadIdx.x;

    for (int i = lane; i < 625; i += 32) {
        float v = trans[i];
        tr[i] = v;
        E[i] = __expf(v);
    }
    __syncwarp();

    const int len = lengths[b];
    const int* tg = tags + b * TT;
    const float* em = g_em + (size_t)b * TT * LL;

    // ---- gold path score ----
    float gp = 0.f;
    for (int t = 1 + lane; t < TT; t += 32) {
        if (t < len) {
            int tp = tg[t - 1], tc = tg[t];
            gp += tr[tp * 25 + tc] + em[t * LL + tc];
        }
    }
    #pragma unroll
    for (int off = 16; off; off >>= 1) gp += __shfl_down_sync(0xffffffffu, gp, off);
    float gold = __shfl_sync(0xffffffffu, gp, 0);
    if (lane == 0) {
        int t0 = tg[0];
        gold += strans[t0] + em[t0];
        gold += etrans[tg[len - 1]];
    }
    gold = __shfl_sync(0xffffffffu, gold, 0);

    // ---- forward algorithm in scaled-prob domain ----
    float A = 0.f, off = 0.f;
    if (lane < LL) A = __expf(strans[lane] + em[lane]);
    As[lane] = A;
    __syncwarp();

    float emn = (lane < LL) ? em[LL + lane] : 0.f;   // prefetch t=1
    for (int t = 1; t < TT; ++t) {
        const float emc = emn;
        const int t2 = (t + 1 < TT) ? (t + 1) : t;
        emn = (lane < LL) ? em[t2 * LL + lane] : 0.f;

        if (t < len) {
            float sa = 0.f, sb = 0.f;
            #pragma unroll
            for (int p = 0; p < 24; p += 2) {
                sa = fmaf(As[p],     E[p * 25 + lane],       sa);
                sb = fmaf(As[p + 1], E[(p + 1) * 25 + lane], sb);
            }
            sa = fmaf(As[24], E[24 * 25 + lane], sa);
            A = (sa + sb) * __expf(emc);
        }
        if ((t & 15) == 15) {   // periodic rescale (growth < e^52 per 16 steps)
            float m = A;
            #pragma unroll
            for (int o = 16; o; o >>= 1) m = fmaxf(m, __shfl_xor_sync(0xffffffffu, m, o));
            off += __logf(m);
            A = __fdividef(A, m);
        }
        __syncwarp();
        As[lane] = A;
        __syncwarp();
    }

    float val = (lane < LL) ? A * __expf(etrans[lane]) : 0.f;
    #pragma unroll
    for (int o = 16; o; o >>= 1) val += __shfl_xor_sync(0xffffffffu, val, o);
    float logZ = off + __logf(val);
    if (lane == 0) g_res[b] = logZ - gold;
}

// ================= Kernel 5: final fixed-order reduction =================
__global__ void __launch_bounds__(128) k_reduce(float* __restrict__ out)
{
    __shared__ float s[128];
    s[threadIdx.x] = g_res[threadIdx.x];
    __syncthreads();
    for (int st = 64; st > 0; st >>= 1) {
        if (threadIdx.x < st) s[threadIdx.x] += s[threadIdx.x + st];
        __syncthreads();
    }
    if (threadIdx.x == 0) out[0] = s[0];
}

// ================= launch =================
extern "C" void kernel_launch(void* const* d_in, const int* in_sizes, int n_in,
                              void* d_out, int out_size)
{
    const int*   tok     = (const int*)  d_in[0];
    const int*   tag     = (const int*)  d_in[1];
    const int*   lengths = (const int*)  d_in[2];
    const float* emb     = (const float*)d_in[3];
    const float* wih_f   = (const float*)d_in[4];
    const float* whh_f   = (const float*)d_in[5];
    const float* bih_f   = (const float*)d_in[6];
    const float* bhh_f   = (const float*)d_in[7];
    const float* wih_b   = (const float*)d_in[8];
    const float* whh_b   = (const float*)d_in[9];
    const float* bih_b   = (const float*)d_in[10];
    const float* bhh_b   = (const float*)d_in[11];
    const float* wtag    = (const float*)d_in[12];
    const float* btag    = (const float*)d_in[13];
    const float* trans   = (const float*)d_in[14];
    const float* strans  = (const float*)d_in[15];
    const float* etrans  = (const float*)d_in[16];
    float* out = (float*)d_out;

    cudaFuncSetAttribute(k_input_proj, cudaFuncAttributeMaxDynamicSharedMemorySize, PROJ_SMEM);
    cudaFuncSetAttribute(k_emit, cudaFuncAttributeMaxDynamicSharedMemorySize, EMIT_SMEM);

    k_input_proj<<<dim3(512, 13), 128, PROJ_SMEM>>>(tok, emb, wih_f, wih_b,
                                                    bih_f, bhh_f, bih_b, bhh_b);
    k_lstm<<<dim3(64, 2), 400>>>(whh_f, whh_b);
    k_emit<<<512, 320, EMIT_SMEM>>>(wtag, btag);
    k_crf<<<128, 32>>>(trans, strans, etrans, tag, lengths);
    k_reduce<<<1, 128>>>(out);
}